// round 11
// baseline (speedup 1.0000x reference)
#include <cuda_runtime.h>
#include <math.h>
#include <stdint.h>

#define NN 4096
#define INF 512
#define OUTF 256
#define NHEAD 4
#define HD 64

// ---------------- scratch (device globals; no allocation allowed) ----------------
__device__ float  g_h [NN * OUTF];     // 4 MB: h = X @ W^T (fp32, row-major)
__device__ float4 g_E1[NN];            // exp(d_j) per head
__device__ float4 g_Ep[NN];            // exp(0.2 d_j)
__device__ float4 g_T [NN];            // exp(-s_i)  (threshold: e1 >= T  <=>  s+d >= 0)
__device__ float4 g_A1[NN];            // exp(s_i)
__device__ float4 g_Ap[NN];            // exp(0.2 s_i)
__device__ float4 g_R1[NN];            // exp(s_i)   / denom_i
__device__ float4 g_Rp[NN];            // exp(0.2s_i)/ denom_i

#define K3_SPLIT 8
__device__ float g_part[K3_SPLIT * NN * OUTF];   // 32 MB split-K partials

// ---------------- f32x2 packed FMA helpers ----------------
__device__ __forceinline__ unsigned long long pack2(float lo, float hi) {
    unsigned long long r;
    asm("mov.b64 %0, {%1,%2};" : "=l"(r) : "f"(lo), "f"(hi));
    return r;
}
__device__ __forceinline__ void unpack2(unsigned long long v, float& lo, float& hi) {
    asm("mov.b64 {%0,%1}, %2;" : "=f"(lo), "=f"(hi) : "l"(v));
}
__device__ __forceinline__ void ffma2(unsigned long long& d, unsigned long long a, unsigned long long b) {
    asm("fma.rn.f32x2 %0, %1, %2, %3;" : "=l"(d) : "l"(a), "l"(b), "l"(d));
}

// ---------------- tf32 helpers (portable mma.sync, no sm_103a-only PTX) ----------------
__device__ __forceinline__ uint32_t to_tf32_bits(float v) {
    uint32_t b; asm("cvt.rna.tf32.f32 %0, %1;" : "=r"(b) : "f"(v));
    return b;
}
__device__ __forceinline__ void mma_tf32(float* d,
                                         uint32_t a0, uint32_t a1, uint32_t a2, uint32_t a3,
                                         uint32_t b0, uint32_t b1) {
    asm volatile("mma.sync.aligned.m16n8k8.row.col.f32.tf32.tf32.f32 "
                 "{%0,%1,%2,%3}, {%4,%5,%6,%7}, {%8,%9}, {%0,%1,%2,%3};"
                 : "+f"(d[0]), "+f"(d[1]), "+f"(d[2]), "+f"(d[3])
                 : "r"(a0), "r"(a1), "r"(a2), "r"(a3), "r"(b0), "r"(b1));
}

// ======================= Kernel 1: h = X @ W^T =======================
#define K1_BK 16
#define K1_PAD 68
__global__ __launch_bounds__(128) void k1_gemm(const float* __restrict__ X,
                                               const float* __restrict__ W) {
    __shared__ float sA[K1_BK][K1_PAD];
    __shared__ float sB[K1_BK][K1_PAD];
    const int m0 = blockIdx.y * 64;
    const int n0 = blockIdx.x * 64;
    const int tid = threadIdx.x;
    const int rg = tid >> 4;
    const int cg = tid & 15;

    unsigned long long acc[8][2];
#pragma unroll
    for (int r = 0; r < 8; r++) { acc[r][0] = 0ull; acc[r][1] = 0ull; }

    for (int k0 = 0; k0 < INF; k0 += K1_BK) {
        __syncthreads();
#pragma unroll
        for (int l = 0; l < 2; l++) {
            int s = tid + l * 128;
            int m = s >> 2, kq = s & 3;
            float4 va = *(const float4*)&X[(size_t)(m0 + m) * INF + k0 + kq * 4];
            sA[kq * 4 + 0][m] = va.x; sA[kq * 4 + 1][m] = va.y;
            sA[kq * 4 + 2][m] = va.z; sA[kq * 4 + 3][m] = va.w;
            float4 vb = *(const float4*)&W[(size_t)(n0 + m) * INF + k0 + kq * 4];
            sB[kq * 4 + 0][m] = vb.x; sB[kq * 4 + 1][m] = vb.y;
            sB[kq * 4 + 2][m] = vb.z; sB[kq * 4 + 3][m] = vb.w;
        }
        __syncthreads();
#pragma unroll
        for (int k = 0; k < K1_BK; k++) {
            float4 a0 = *(const float4*)&sA[k][rg * 8];
            float4 a1 = *(const float4*)&sA[k][rg * 8 + 4];
            float4 b  = *(const float4*)&sB[k][cg * 4];
            unsigned long long b20 = pack2(b.x, b.y);
            unsigned long long b21 = pack2(b.z, b.w);
            float ar[8] = {a0.x, a0.y, a0.z, a0.w, a1.x, a1.y, a1.z, a1.w};
#pragma unroll
            for (int r = 0; r < 8; r++) {
                unsigned long long a2 = pack2(ar[r], ar[r]);
                ffma2(acc[r][0], a2, b20);
                ffma2(acc[r][1], a2, b21);
            }
        }
    }
#pragma unroll
    for (int r = 0; r < 8; r++) {
        float x0, x1, x2, x3;
        unpack2(acc[r][0], x0, x1);
        unpack2(acc[r][1], x2, x3);
        *(float4*)&g_h[(size_t)(m0 + rg * 8 + r) * OUTF + n0 + cg * 4] =
            make_float4(x0, x1, x2, x3);
    }
}

// ======================= Kernel 1b: per-node attention stats =======================
__global__ __launch_bounds__(128) void k1b_stats(const float* __restrict__ a) {
    const int i = blockIdx.x;
    const int head = threadIdx.x >> 5;
    const int lane = threadIdx.x & 31;
    float h0 = g_h[i * OUTF + head * HD + lane];
    float h1 = g_h[i * OUTF + head * HD + 32 + lane];
    const float* ah = a + head * 2 * HD;
    float s = h0 * ah[lane] + h1 * ah[32 + lane];
    float d = h0 * ah[HD + lane] + h1 * ah[HD + 32 + lane];
#pragma unroll
    for (int o = 16; o > 0; o >>= 1) {
        s += __shfl_xor_sync(0xffffffffu, s, o);
        d += __shfl_xor_sync(0xffffffffu, d, o);
    }
    if (lane == 0) {
        ((float*)&g_T [i])[head] = expf(-s);
        ((float*)&g_A1[i])[head] = expf(s);
        ((float*)&g_Ap[i])[head] = expf(0.2f * s);
        ((float*)&g_E1[i])[head] = expf(d);
        ((float*)&g_Ep[i])[head] = expf(0.2f * d);
    }
}

// ======================= Kernel 2: softmax denominators =======================
#define K2_ROWS 32
#define K2_SMEM ((8 * NN + 72) * 4)
__global__ __launch_bounds__(256) void k2_denom(const float* __restrict__ adj) {
    extern __shared__ float sm[];
    float4* sE1 = (float4*)sm;
    float4* sEp = (float4*)(sm + 4 * NN);
    float*  red = sm + 8 * NN;
    const int tid = threadIdx.x;

    for (int idx = tid; idx < NN; idx += 256) { sE1[idx] = g_E1[idx]; sEp[idx] = g_Ep[idx]; }
    __syncthreads();

    const int row0 = blockIdx.x * K2_ROWS;
    for (int r = 0; r < K2_ROWS; r++) {
        const int i = row0 + r;
        const float4 T = g_T[i];
        float S1x = 0.f, S1y = 0.f, S1z = 0.f, S1w = 0.f;
        float Spx = 0.f, Spy = 0.f, Spz = 0.f, Spw = 0.f;
        const float* arow = adj + (size_t)i * NN;
#pragma unroll
        for (int u = 0; u < NN / 256; u++) {
            int j = tid + u * 256;
            float av = arow[j];
            if (av > 0.1f) {
                float4 e1 = sE1[j], ep = sEp[j];
                if (e1.x >= T.x) S1x += e1.x; else Spx += ep.x;
                if (e1.y >= T.y) S1y += e1.y; else Spy += ep.y;
                if (e1.z >= T.z) S1z += e1.z; else Spz += ep.z;
                if (e1.w >= T.w) S1w += e1.w; else Spw += ep.w;
            }
        }
        float vals[8] = {S1x, S1y, S1z, S1w, Spx, Spy, Spz, Spw};
#pragma unroll
        for (int v = 0; v < 8; v++) {
            float x = vals[v];
#pragma unroll
            for (int o = 16; o > 0; o >>= 1) x += __shfl_xor_sync(0xffffffffu, x, o);
            if ((tid & 31) == 0) red[(tid >> 5) * 8 + v] = x;
        }
        __syncthreads();
        if (tid < 8) {
            float x = 0.f;
#pragma unroll
            for (int w = 0; w < 8; w++) x += red[w * 8 + tid];
            red[64 + tid] = x;
        }
        __syncthreads();
        if (tid < 4) {
            float a1 = ((const float*)&g_A1[i])[tid];
            float ap = ((const float*)&g_Ap[i])[tid];
            float den = a1 * red[64 + tid] + ap * red[64 + 4 + tid];
            float inv = (den > 0.f) ? 1.f / den : 0.f;
            ((float*)&g_R1[i])[tid] = a1 * inv;
            ((float*)&g_Rp[i])[tid] = ap * inv;
        }
        __syncthreads();
    }
}

// ======================= Kernel 3: tf32 mma.sync split-K =======================
// grid (2 n-tiles, 32 i-tiles, 8 splits), 256 thr (8 warps: 4m x 2n).
// CTA tile 128m x 128n, K-chunk 64. A = attention weights (computed in-kernel,
// tf32) in sW[m][k] stride 68 -> (4m+k)%32 banks: m16k8 frag loads conflict-free.
// B = h tile [k][n] stride 136 -> (8k+n)%32 banks: k8n8 frag loads conflict-free.
#define KC 64
#define SWA 68
#define SWB 136
#define SA_FL (128 * SWA)                 // 8704 floats
#define SB_FL (KC * SWB)                  // 8704 floats
#define K3_SMEM_TOT ((SA_FL + SB_FL) * 4 + 3 * 128 * 16)   // 75776 B
__global__ __launch_bounds__(256, 2) void k3_out(const float* __restrict__ adj) {
    extern __shared__ float sm3[];
    float*  sW  = sm3;                     // [128][68]
    float*  sB  = sm3 + SA_FL;             // [64][136]
    float4* sT  = (float4*)(sm3 + SA_FL + SB_FL);
    float4* sR1 = sT + 128;
    float4* sRp = sR1 + 128;
    const uint32_t* sWu = (const uint32_t*)sW;
    const uint32_t* sBu = (const uint32_t*)sB;

    const int tid = threadIdx.x;
    const int wid = tid >> 5;
    const int lane = tid & 31;
    const int cn0 = blockIdx.x * 128;
    const int row0 = blockIdx.y * 128;
    const int split = blockIdx.z;
    const int jbeg = split * (NN / K3_SPLIT);

    const int warp_m = wid & 3;            // rows warp_m*32 .. +31
    const int warp_n = wid >> 2;           // cols warp_n*64 .. +63

    if (tid < 128) {
        sT[tid] = g_T[row0 + tid]; sR1[tid] = g_R1[row0 + tid]; sRp[tid] = g_Rp[row0 + tid];
    }

    const int kk  = tid & 63;              // w-phase: k (=j) index
    const int grp = tid >> 6;              // w-phase: rows grp*32..+31

    float acc[2][8][4];
#pragma unroll
    for (int mt = 0; mt < 2; mt++)
#pragma unroll
        for (int nf = 0; nf < 8; nf++)
#pragma unroll
            for (int q = 0; q < 4; q++) acc[mt][nf][q] = 0.f;

    __syncthreads();

    for (int c = 0; c < 8; c++) {
        const int j0 = jbeg + c * KC;
        // ---- A: attention-weight tile w[m][kk] (tf32) ----
        float4 e1 = g_E1[j0 + kk];
        float4 ep = g_Ep[j0 + kk];
#pragma unroll 4
        for (int rr = 0; rr < 32; rr++) {
            int m = grp * 32 + rr;
            float av = adj[(size_t)(row0 + m) * NN + j0 + kk];
            float w = 0.f;
            if (av > 0.1f) {
                float4 T = sT[m], R1 = sR1[m], Rp = sRp[m];
                float s0 = (e1.x >= T.x) ? R1.x * e1.x : Rp.x * ep.x;
                float s1 = (e1.y >= T.y) ? R1.y * e1.y : Rp.y * ep.y;
                float s2 = (e1.z >= T.z) ? R1.z * e1.z : Rp.z * ep.z;
                float s3 = (e1.w >= T.w) ? R1.w * e1.w : Rp.w * ep.w;
                w = 0.25f * ((s0 + s1) + (s2 + s3));
            }
            ((uint32_t*)sW)[m * SWA + kk] = to_tf32_bits(w);
        }
        // ---- B: h tile [k][n] (tf32), rows j0..j0+63, cols cn0..cn0+127 ----
#pragma unroll
        for (int l = 0; l < 8; l++) {
            int s = tid + l * 256;         // 2048 float4 slots
            int k = s >> 5, c4 = s & 31;
            float4 v = *(const float4*)&g_h[(size_t)(j0 + k) * OUTF + cn0 + c4 * 4];
            uint32_t* dst = (uint32_t*)&sB[k * SWB + c4 * 4];
            dst[0] = to_tf32_bits(v.x); dst[1] = to_tf32_bits(v.y);
            dst[2] = to_tf32_bits(v.z); dst[3] = to_tf32_bits(v.w);
        }
        __syncthreads();
        // ---- mma: 8 k8-steps, 2 m16 x 8 n8 frags per warp ----
        const int lr = lane >> 2;          // 0..7
        const int lc = lane & 3;           // 0..3
#pragma unroll
        for (int ks = 0; ks < 8; ks++) {
            const int k0 = ks * 8;
            uint32_t af[2][4];
#pragma unroll
            for (int mt = 0; mt < 2; mt++) {
                int rm = (warp_m * 32 + mt * 16 + lr) * SWA + k0 + lc;
                af[mt][0] = sWu[rm];
                af[mt][1] = sWu[rm + 8 * SWA];
                af[mt][2] = sWu[rm + 4];
                af[mt][3] = sWu[rm + 8 * SWA + 4];
            }
#pragma unroll
            for (int nf = 0; nf < 8; nf++) {
                int nb = (k0 + lc) * SWB + warp_n * 64 + nf * 8 + lr;
                uint32_t b0 = sBu[nb];
                uint32_t b1 = sBu[nb + 4 * SWB];
                mma_tf32(acc[0][nf], af[0][0], af[0][1], af[0][2], af[0][3], b0, b1);
                mma_tf32(acc[1][nf], af[1][0], af[1][1], af[1][2], af[1][3], b0, b1);
            }
        }
        __syncthreads();
    }
    // ---- epilogue: fragment-mapped stores to split partials ----
    float* pbase = g_part + (size_t)split * NN * OUTF;
    const int lr = lane >> 2;
    const int lc = lane & 3;
#pragma unroll
    for (int mt = 0; mt < 2; mt++) {
        int r0g = row0 + warp_m * 32 + mt * 16 + lr;
#pragma unroll
        for (int nf = 0; nf < 8; nf++) {
            int col = cn0 + warp_n * 64 + nf * 8 + 2 * lc;
            *(float2*)&pbase[(size_t)r0g * OUTF + col] =
                make_float2(acc[mt][nf][0], acc[mt][nf][1]);
            *(float2*)&pbase[(size_t)(r0g + 8) * OUTF + col] =
                make_float2(acc[mt][nf][2], acc[mt][nf][3]);
        }
    }
}

// ======================= Kernel 4: reduce splits + bias =======================
__global__ __launch_bounds__(256) void k4_reduce(const float* __restrict__ bias,
                                                 float* __restrict__ out) {
    int idx = blockIdx.x * 256 + threadIdx.x;
    int col4 = idx & (OUTF / 4 - 1);
    float4 s = ((const float4*)bias)[col4];
    const float4* p = (const float4*)g_part;
#pragma unroll
    for (int k = 0; k < K3_SPLIT; k++) {
        float4 v = p[(size_t)k * (NN * OUTF / 4) + idx];
        s.x += v.x; s.y += v.y; s.z += v.z; s.w += v.w;
    }
    ((float4*)out)[idx] = s;
}

// ======================= launch =======================
extern "C" void kernel_launch(void* const* d_in, const int* in_sizes, int n_in,
                              void* d_out, int out_size) {
    const float* features = (const float*)d_in[0];
    const float* adj      = (const float*)d_in[1];
    const float* W        = (const float*)d_in[2];
    const float* a        = (const float*)d_in[3];
    const float* bias     = (const float*)d_in[4];
    float* out = (float*)d_out;

    cudaFuncSetAttribute(k2_denom, cudaFuncAttributeMaxDynamicSharedMemorySize, K2_SMEM);
    cudaFuncSetAttribute(k3_out,   cudaFuncAttributeMaxDynamicSharedMemorySize, K3_SMEM_TOT);

    k1_gemm<<<dim3(OUTF / 64, NN / 64), 128>>>(features, W);
    k1b_stats<<<NN, 128>>>(a);
    k2_denom<<<NN / K2_ROWS, 256, K2_SMEM>>>(adj);
    k3_out<<<dim3(2, NN / 128, K3_SPLIT), 256, K3_SMEM_TOT>>>(adj);
    k4_reduce<<<NN * OUTF / 4 / 256, 256>>>(bias, out);
}

// round 13
// speedup vs baseline: 1.1325x; 1.1325x over previous
#include <cuda_runtime.h>
#include <math.h>
#include <stdint.h>

#define NN 4096
#define INF 512
#define OUTF 256
#define NHEAD 4
#define HD 64

// ---------------- scratch (device globals; no allocation allowed) ----------------
__device__ float  g_h [NN * OUTF];     // 4 MB: h = X @ W^T (fp32, row-major)
__device__ float4 g_E1[NN];            // exp(d_j) per head
__device__ float4 g_Ep[NN];            // exp(0.2 d_j)
__device__ float4 g_T [NN];            // exp(-s_i)  (threshold: e1 >= T  <=>  s+d >= 0)
__device__ float4 g_A1[NN];            // exp(s_i)
__device__ float4 g_Ap[NN];            // exp(0.2 s_i)
__device__ float4 g_R1[NN];            // exp(s_i)   / denom_i
__device__ float4 g_Rp[NN];            // exp(0.2s_i)/ denom_i

#define K3_SPLIT 8
__device__ float g_part[K3_SPLIT * NN * OUTF];   // 32 MB split-K partials

// ---------------- f32x2 packed FMA helpers ----------------
__device__ __forceinline__ unsigned long long pack2(float lo, float hi) {
    unsigned long long r;
    asm("mov.b64 %0, {%1,%2};" : "=l"(r) : "f"(lo), "f"(hi));
    return r;
}
__device__ __forceinline__ void unpack2(unsigned long long v, float& lo, float& hi) {
    asm("mov.b64 {%0,%1}, %2;" : "=f"(lo), "=f"(hi) : "l"(v));
}
__device__ __forceinline__ void ffma2(unsigned long long& d, unsigned long long a, unsigned long long b) {
    asm("fma.rn.f32x2 %0, %1, %2, %3;" : "=l"(d) : "l"(a), "l"(b), "l"(d));
}

// ---------------- tf32 helpers (portable mma.sync, no sm_103a-only PTX) ----------------
__device__ __forceinline__ uint32_t to_tf32_bits(float v) {
    uint32_t b; asm("cvt.rna.tf32.f32 %0, %1;" : "=r"(b) : "f"(v));
    return b;
}
__device__ __forceinline__ void mma_tf32(float* d,
                                         uint32_t a0, uint32_t a1, uint32_t a2, uint32_t a3,
                                         uint32_t b0, uint32_t b1) {
    asm volatile("mma.sync.aligned.m16n8k8.row.col.f32.tf32.tf32.f32 "
                 "{%0,%1,%2,%3}, {%4,%5,%6,%7}, {%8,%9}, {%0,%1,%2,%3};"
                 : "+f"(d[0]), "+f"(d[1]), "+f"(d[2]), "+f"(d[3])
                 : "r"(a0), "r"(a1), "r"(a2), "r"(a3), "r"(b0), "r"(b1));
}

// ======================= Kernel 1: h = X @ W^T =======================
#define K1_BK 16
#define K1_PAD 68
__global__ __launch_bounds__(128) void k1_gemm(const float* __restrict__ X,
                                               const float* __restrict__ W) {
    __shared__ float sA[K1_BK][K1_PAD];
    __shared__ float sB[K1_BK][K1_PAD];
    const int m0 = blockIdx.y * 64;
    const int n0 = blockIdx.x * 64;
    const int tid = threadIdx.x;
    const int rg = tid >> 4;
    const int cg = tid & 15;

    unsigned long long acc[8][2];
#pragma unroll
    for (int r = 0; r < 8; r++) { acc[r][0] = 0ull; acc[r][1] = 0ull; }

    for (int k0 = 0; k0 < INF; k0 += K1_BK) {
        __syncthreads();
#pragma unroll
        for (int l = 0; l < 2; l++) {
            int s = tid + l * 128;
            int m = s >> 2, kq = s & 3;
            float4 va = *(const float4*)&X[(size_t)(m0 + m) * INF + k0 + kq * 4];
            sA[kq * 4 + 0][m] = va.x; sA[kq * 4 + 1][m] = va.y;
            sA[kq * 4 + 2][m] = va.z; sA[kq * 4 + 3][m] = va.w;
            float4 vb = *(const float4*)&W[(size_t)(n0 + m) * INF + k0 + kq * 4];
            sB[kq * 4 + 0][m] = vb.x; sB[kq * 4 + 1][m] = vb.y;
            sB[kq * 4 + 2][m] = vb.z; sB[kq * 4 + 3][m] = vb.w;
        }
        __syncthreads();
#pragma unroll
        for (int k = 0; k < K1_BK; k++) {
            float4 a0 = *(const float4*)&sA[k][rg * 8];
            float4 a1 = *(const float4*)&sA[k][rg * 8 + 4];
            float4 b  = *(const float4*)&sB[k][cg * 4];
            unsigned long long b20 = pack2(b.x, b.y);
            unsigned long long b21 = pack2(b.z, b.w);
            float ar[8] = {a0.x, a0.y, a0.z, a0.w, a1.x, a1.y, a1.z, a1.w};
#pragma unroll
            for (int r = 0; r < 8; r++) {
                unsigned long long a2 = pack2(ar[r], ar[r]);
                ffma2(acc[r][0], a2, b20);
                ffma2(acc[r][1], a2, b21);
            }
        }
    }
#pragma unroll
    for (int r = 0; r < 8; r++) {
        float x0, x1, x2, x3;
        unpack2(acc[r][0], x0, x1);
        unpack2(acc[r][1], x2, x3);
        *(float4*)&g_h[(size_t)(m0 + rg * 8 + r) * OUTF + n0 + cg * 4] =
            make_float4(x0, x1, x2, x3);
    }
}

// ======================= Kernel 1b: per-node attention stats =======================
__global__ __launch_bounds__(128) void k1b_stats(const float* __restrict__ a) {
    const int i = blockIdx.x;
    const int head = threadIdx.x >> 5;
    const int lane = threadIdx.x & 31;
    float h0 = g_h[i * OUTF + head * HD + lane];
    float h1 = g_h[i * OUTF + head * HD + 32 + lane];
    const float* ah = a + head * 2 * HD;
    float s = h0 * ah[lane] + h1 * ah[32 + lane];
    float d = h0 * ah[HD + lane] + h1 * ah[HD + 32 + lane];
#pragma unroll
    for (int o = 16; o > 0; o >>= 1) {
        s += __shfl_xor_sync(0xffffffffu, s, o);
        d += __shfl_xor_sync(0xffffffffu, d, o);
    }
    if (lane == 0) {
        ((float*)&g_T [i])[head] = expf(-s);
        ((float*)&g_A1[i])[head] = expf(s);
        ((float*)&g_Ap[i])[head] = expf(0.2f * s);
        ((float*)&g_E1[i])[head] = expf(d);
        ((float*)&g_Ep[i])[head] = expf(0.2f * d);
    }
}

// ======================= Kernel 2: softmax denominators =======================
// warp-per-row, float4 adj loads, no block barriers. grid NN/8, 256 thr.
__global__ __launch_bounds__(256) void k2_denom(const float* __restrict__ adj) {
    const int wid = threadIdx.x >> 5;
    const int lane = threadIdx.x & 31;
    const int i = blockIdx.x * 8 + wid;
    const float4 T = g_T[i];
    float4 S1 = make_float4(0.f, 0.f, 0.f, 0.f);
    float4 Sp = make_float4(0.f, 0.f, 0.f, 0.f);
    const float4* arow = (const float4*)(adj + (size_t)i * NN);
#pragma unroll 4
    for (int k = 0; k < NN / 128; k++) {       // 32 float4 per lane, independent
        int j4 = k * 32 + lane;
        float4 av = arow[j4];
        int j = j4 * 4;
        float mq[4] = {av.x, av.y, av.z, av.w};
#pragma unroll
        for (int q = 0; q < 4; q++) {
            if (mq[q] > 0.1f) {
                float4 e1 = g_E1[j + q], ep = g_Ep[j + q];
                if (e1.x >= T.x) S1.x += e1.x; else Sp.x += ep.x;
                if (e1.y >= T.y) S1.y += e1.y; else Sp.y += ep.y;
                if (e1.z >= T.z) S1.z += e1.z; else Sp.z += ep.z;
                if (e1.w >= T.w) S1.w += e1.w; else Sp.w += ep.w;
            }
        }
    }
#pragma unroll
    for (int o = 16; o > 0; o >>= 1) {
        S1.x += __shfl_xor_sync(0xffffffffu, S1.x, o);
        S1.y += __shfl_xor_sync(0xffffffffu, S1.y, o);
        S1.z += __shfl_xor_sync(0xffffffffu, S1.z, o);
        S1.w += __shfl_xor_sync(0xffffffffu, S1.w, o);
        Sp.x += __shfl_xor_sync(0xffffffffu, Sp.x, o);
        Sp.y += __shfl_xor_sync(0xffffffffu, Sp.y, o);
        Sp.z += __shfl_xor_sync(0xffffffffu, Sp.z, o);
        Sp.w += __shfl_xor_sync(0xffffffffu, Sp.w, o);
    }
    if (lane == 0) {
        float4 a1 = g_A1[i], ap = g_Ap[i];
        float4 r1, rp;
        float d0 = a1.x * S1.x + ap.x * Sp.x;
        float d1 = a1.y * S1.y + ap.y * Sp.y;
        float d2 = a1.z * S1.z + ap.z * Sp.z;
        float d3 = a1.w * S1.w + ap.w * Sp.w;
        float i0 = d0 > 0.f ? 1.f / d0 : 0.f;
        float i1 = d1 > 0.f ? 1.f / d1 : 0.f;
        float i2 = d2 > 0.f ? 1.f / d2 : 0.f;
        float i3 = d3 > 0.f ? 1.f / d3 : 0.f;
        r1 = make_float4(a1.x * i0, a1.y * i1, a1.z * i2, a1.w * i3);
        rp = make_float4(ap.x * i0, ap.y * i1, ap.z * i2, ap.w * i3);
        g_R1[i] = r1; g_Rp[i] = rp;
    }
}

// ======================= Kernel 3: tf32 mma.sync split-K, register-pipelined =======================
// grid (2 n-tiles, 32 i-tiles, 8 splits), 512 thr (16 warps: warp_m=wid&7 m16, warp_n=wid>>3 n64).
// CTA tile 128m x 128n, K-chunk 64. adj + h tiles for chunk c+1 prefetched into
// registers during chunk c's mma phase (latency hidden behind tensor work).
// sW[m][k] stride 68, sB[k][n] stride 136: fragment LDS conflict-free.
#define KC 64
#define SWA 68
#define SWB 136
#define SA_FL (128 * SWA)                 // 8704 floats
#define SB_FL (KC * SWB)                  // 8704 floats
#define K3_SMEM_TOT ((SA_FL + SB_FL) * 4 + 3 * 128 * 16)   // 75776 B
__global__ __launch_bounds__(512, 1) void k3_out(const float* __restrict__ adj) {
    extern __shared__ float sm3[];
    float*  sW  = sm3;                     // [128][68]
    float*  sB  = sm3 + SA_FL;             // [64][136]
    float4* sT  = (float4*)(sm3 + SA_FL + SB_FL);
    float4* sR1 = sT + 128;
    float4* sRp = sR1 + 128;
    const uint32_t* sWu = (const uint32_t*)sW;
    const uint32_t* sBu = (const uint32_t*)sB;

    const int tid = threadIdx.x;
    const int wid = tid >> 5;
    const int lane = tid & 31;
    const int cn0 = blockIdx.x * 128;
    const int row0 = blockIdx.y * 128;
    const int split = blockIdx.z;
    const int jbeg = split * (NN / K3_SPLIT);

    const int warp_m = wid & 7;            // rows warp_m*16 .. +15
    const int warp_n = wid >> 3;           // cols warp_n*64 .. +63

    if (tid < 128) {
        sT[tid] = g_T[row0 + tid]; sR1[tid] = g_R1[row0 + tid]; sRp[tid] = g_Rp[row0 + tid];
    }

    // w-phase mapping: thread covers rows mr..mr+3, j-group jg (4 consecutive j)
    const int jg = tid & 15;
    const int mr = (tid >> 4) * 4;
    const float4* adj4 = (const float4*)adj;
    const float4* gh4 = (const float4*)g_h;

    float acc[8][4];
#pragma unroll
    for (int nf = 0; nf < 8; nf++)
#pragma unroll
        for (int q = 0; q < 4; q++) acc[nf][q] = 0.f;

    // ---- prefetch chunk 0 ----
    float4 aj[4], bj[4];
#pragma unroll
    for (int l = 0; l < 4; l++)
        aj[l] = adj4[(size_t)(row0 + mr + l) * (NN / 4) + (jbeg >> 2) + jg];
#pragma unroll
    for (int l = 0; l < 4; l++) {
        int s = tid + l * 512;
        int k = s >> 5, n4 = s & 31;
        bj[l] = gh4[(size_t)(jbeg + k) * (OUTF / 4) + (cn0 >> 2) + n4];
    }
    __syncthreads();   // sT/sR1/sRp ready

    const int lr = lane >> 2;
    const int lc = lane & 3;

    for (int c = 0; c < 8; c++) {
        const int j0 = jbeg + c * KC;
        if (c > 0) __syncthreads();        // prior mma done reading smem

        // ---- store B tile (tf32) ----
#pragma unroll
        for (int l = 0; l < 4; l++) {
            int s = tid + l * 512;
            int k = s >> 5, n4 = s & 31;
            uint32_t* dst = (uint32_t*)&sB[k * SWB + n4 * 4];
            dst[0] = to_tf32_bits(bj[l].x); dst[1] = to_tf32_bits(bj[l].y);
            dst[2] = to_tf32_bits(bj[l].z); dst[3] = to_tf32_bits(bj[l].w);
        }
        // ---- compute + store w tile (tf32) ----
        {
            float4 e1q[4], epq[4];
#pragma unroll
            for (int q = 0; q < 4; q++) {
                e1q[q] = g_E1[j0 + jg * 4 + q];
                epq[q] = g_Ep[j0 + jg * 4 + q];
            }
#pragma unroll
            for (int l = 0; l < 4; l++) {
                int m = mr + l;
                float4 T = sT[m], R1 = sR1[m], Rp = sRp[m];
                float av[4] = {aj[l].x, aj[l].y, aj[l].z, aj[l].w};
                uint32_t wv[4];
#pragma unroll
                for (int q = 0; q < 4; q++) {
                    float w = 0.f;
                    if (av[q] > 0.1f) {
                        float4 e1 = e1q[q], ep = epq[q];
                        float s0 = (e1.x >= T.x) ? R1.x * e1.x : Rp.x * ep.x;
                        float s1 = (e1.y >= T.y) ? R1.y * e1.y : Rp.y * ep.y;
                        float s2 = (e1.z >= T.z) ? R1.z * e1.z : Rp.z * ep.z;
                        float s3 = (e1.w >= T.w) ? R1.w * e1.w : Rp.w * ep.w;
                        w = 0.25f * ((s0 + s1) + (s2 + s3));
                    }
                    wv[q] = to_tf32_bits(w);
                }
                *(uint4*)&sW[m * SWA + jg * 4] = make_uint4(wv[0], wv[1], wv[2], wv[3]);
            }
        }
        __syncthreads();                   // tiles ready

        // ---- prefetch chunk c+1 (overlaps mma below) ----
        if (c < 7) {
            const int jn = j0 + KC;
#pragma unroll
            for (int l = 0; l < 4; l++)
                aj[l] = adj4[(size_t)(row0 + mr + l) * (NN / 4) + (jn >> 2) + jg];
#pragma unroll
            for (int l = 0; l < 4; l++) {
                int s = tid + l * 512;
                int k = s >> 5, n4 = s & 31;
                bj[l] = gh4[(size_t)(jn + k) * (OUTF / 4) + (cn0 >> 2) + n4];
            }
        }

        // ---- mma: 8 k8-steps, 1 m16 x 8 n8 frags per warp ----
#pragma unroll
        for (int ks = 0; ks < 8; ks++) {
            const int k0 = ks * 8;
            int rm = (warp_m * 16 + lr) * SWA + k0 + lc;
            uint32_t a0 = sWu[rm];
            uint32_t a1 = sWu[rm + 8 * SWA];
            uint32_t a2 = sWu[rm + 4];
            uint32_t a3 = sWu[rm + 8 * SWA + 4];
#pragma unroll
            for (int nf = 0; nf < 8; nf++) {
                int nb = (k0 + lc) * SWB + warp_n * 64 + nf * 8 + lr;
                uint32_t b0 = sBu[nb];
                uint32_t b1 = sBu[nb + 4 * SWB];
                mma_tf32(acc[nf], a0, a1, a2, a3, b0, b1);
            }
        }
    }
    // ---- epilogue: fragment-mapped stores to split partials ----
    float* pbase = g_part + (size_t)split * NN * OUTF;
    int r0g = row0 + warp_m * 16 + lr;
#pragma unroll
    for (int nf = 0; nf < 8; nf++) {
        int col = cn0 + warp_n * 64 + nf * 8 + 2 * lc;
        *(float2*)&pbase[(size_t)r0g * OUTF + col] =
            make_float2(acc[nf][0], acc[nf][1]);
        *(float2*)&pbase[(size_t)(r0g + 8) * OUTF + col] =
            make_float2(acc[nf][2], acc[nf][3]);
    }
}

// ======================= Kernel 4: reduce splits + bias =======================
__global__ __launch_bounds__(256) void k4_reduce(const float* __restrict__ bias,
                                                 float* __restrict__ out) {
    int idx = blockIdx.x * 256 + threadIdx.x;
    int col4 = idx & (OUTF / 4 - 1);
    float4 s = ((const float4*)bias)[col4];
    const float4* p = (const float4*)g_part;
#pragma unroll
    for (int k = 0; k < K3_SPLIT; k++) {
        float4 v = p[(size_t)k * (NN * OUTF / 4) + idx];
        s.x += v.x; s.y += v.y; s.z += v.z; s.w += v.w;
    }
    ((float4*)out)[idx] = s;
}

// ======================= launch =======================
extern "C" void kernel_launch(void* const* d_in, const int* in_sizes, int n_in,
                              void* d_out, int out_size) {
    const float* features = (const float*)d_in[0];
    const float* adj      = (const float*)d_in[1];
    const float* W        = (const float*)d_in[2];
    const float* a        = (const float*)d_in[3];
    const float* bias     = (const float*)d_in[4];
    float* out = (float*)d_out;

    cudaFuncSetAttribute(k3_out, cudaFuncAttributeMaxDynamicSharedMemorySize, K3_SMEM_TOT);

    k1_gemm<<<dim3(OUTF / 64, NN / 64), 128>>>(features, W);
    k1b_stats<<<NN, 128>>>(a);
    k2_denom<<<NN / 8, 256>>>(adj);
    k3_out<<<dim3(2, NN / 128, K3_SPLIT), 512, K3_SMEM_TOT>>>(adj);
    k4_reduce<<<NN * OUTF / 4 / 256, 256>>>(bias, out);
}

// round 15
// speedup vs baseline: 1.1683x; 1.0316x over previous
#include <cuda_runtime.h>
#include <math.h>
#include <stdint.h>

#define NN 4096
#define INF 512
#define OUTF 256
#define NHEAD 4
#define HD 64

// ---------------- scratch (device globals; no allocation allowed) ----------------
__device__ float  g_h [NN * OUTF];     // 4 MB: h = X @ W^T (fp32, row-major)
__device__ float4 g_E1[NN];            // exp(d_j) per head
__device__ float4 g_Ep[NN];            // exp(0.2 d_j)
__device__ float4 g_T [NN];            // exp(-s_i)  (threshold: e1 >= T  <=>  s+d >= 0)
__device__ float4 g_A1[NN];            // exp(s_i)
__device__ float4 g_Ap[NN];            // exp(0.2 s_i)
__device__ float4 g_R1[NN];            // exp(s_i)   / denom_i
__device__ float4 g_Rp[NN];            // exp(0.2s_i)/ denom_i

#define K3_SPLIT 8
__device__ float g_part[K3_SPLIT * NN * OUTF];   // 32 MB split-K partials

// ---------------- f32x2 packed FMA helpers ----------------
__device__ __forceinline__ unsigned long long pack2(float lo, float hi) {
    unsigned long long r;
    asm("mov.b64 %0, {%1,%2};" : "=l"(r) : "f"(lo), "f"(hi));
    return r;
}
__device__ __forceinline__ void unpack2(unsigned long long v, float& lo, float& hi) {
    asm("mov.b64 {%0,%1}, %2;" : "=f"(lo), "=f"(hi) : "l"(v));
}
__device__ __forceinline__ void ffma2(unsigned long long& d, unsigned long long a, unsigned long long b) {
    asm("fma.rn.f32x2 %0, %1, %2, %3;" : "=l"(d) : "l"(a), "l"(b), "l"(d));
}

// ---------------- tf32 helpers (portable mma.sync, no sm_103a-only PTX) ----------------
__device__ __forceinline__ uint32_t to_tf32_bits(float v) {
    uint32_t b; asm("cvt.rna.tf32.f32 %0, %1;" : "=r"(b) : "f"(v));
    return b;
}
__device__ __forceinline__ void mma_tf32(float* d,
                                         uint32_t a0, uint32_t a1, uint32_t a2, uint32_t a3,
                                         uint32_t b0, uint32_t b1) {
    asm volatile("mma.sync.aligned.m16n8k8.row.col.f32.tf32.tf32.f32 "
                 "{%0,%1,%2,%3}, {%4,%5,%6,%7}, {%8,%9}, {%0,%1,%2,%3};"
                 : "+f"(d[0]), "+f"(d[1]), "+f"(d[2]), "+f"(d[3])
                 : "r"(a0), "r"(a1), "r"(a2), "r"(a3), "r"(b0), "r"(b1));
}

// ======================= Kernel 1: h = X @ W^T =======================
#define K1_BK 16
#define K1_PAD 68
__global__ __launch_bounds__(128) void k1_gemm(const float* __restrict__ X,
                                               const float* __restrict__ W) {
    __shared__ float sA[K1_BK][K1_PAD];
    __shared__ float sB[K1_BK][K1_PAD];
    const int m0 = blockIdx.y * 64;
    const int n0 = blockIdx.x * 64;
    const int tid = threadIdx.x;
    const int rg = tid >> 4;
    const int cg = tid & 15;

    unsigned long long acc[8][2];
#pragma unroll
    for (int r = 0; r < 8; r++) { acc[r][0] = 0ull; acc[r][1] = 0ull; }

    for (int k0 = 0; k0 < INF; k0 += K1_BK) {
        __syncthreads();
#pragma unroll
        for (int l = 0; l < 2; l++) {
            int s = tid + l * 128;
            int m = s >> 2, kq = s & 3;
            float4 va = *(const float4*)&X[(size_t)(m0 + m) * INF + k0 + kq * 4];
            sA[kq * 4 + 0][m] = va.x; sA[kq * 4 + 1][m] = va.y;
            sA[kq * 4 + 2][m] = va.z; sA[kq * 4 + 3][m] = va.w;
            float4 vb = *(const float4*)&W[(size_t)(n0 + m) * INF + k0 + kq * 4];
            sB[kq * 4 + 0][m] = vb.x; sB[kq * 4 + 1][m] = vb.y;
            sB[kq * 4 + 2][m] = vb.z; sB[kq * 4 + 3][m] = vb.w;
        }
        __syncthreads();
#pragma unroll
        for (int k = 0; k < K1_BK; k++) {
            float4 a0 = *(const float4*)&sA[k][rg * 8];
            float4 a1 = *(const float4*)&sA[k][rg * 8 + 4];
            float4 b  = *(const float4*)&sB[k][cg * 4];
            unsigned long long b20 = pack2(b.x, b.y);
            unsigned long long b21 = pack2(b.z, b.w);
            float ar[8] = {a0.x, a0.y, a0.z, a0.w, a1.x, a1.y, a1.z, a1.w};
#pragma unroll
            for (int r = 0; r < 8; r++) {
                unsigned long long a2 = pack2(ar[r], ar[r]);
                ffma2(acc[r][0], a2, b20);
                ffma2(acc[r][1], a2, b21);
            }
        }
    }
#pragma unroll
    for (int r = 0; r < 8; r++) {
        float x0, x1, x2, x3;
        unpack2(acc[r][0], x0, x1);
        unpack2(acc[r][1], x2, x3);
        *(float4*)&g_h[(size_t)(m0 + rg * 8 + r) * OUTF + n0 + cg * 4] =
            make_float4(x0, x1, x2, x3);
    }
}

// ======================= Kernel 1b: per-node attention stats =======================
__global__ __launch_bounds__(128) void k1b_stats(const float* __restrict__ a) {
    const int i = blockIdx.x;
    const int head = threadIdx.x >> 5;
    const int lane = threadIdx.x & 31;
    float h0 = g_h[i * OUTF + head * HD + lane];
    float h1 = g_h[i * OUTF + head * HD + 32 + lane];
    const float* ah = a + head * 2 * HD;
    float s = h0 * ah[lane] + h1 * ah[32 + lane];
    float d = h0 * ah[HD + lane] + h1 * ah[HD + 32 + lane];
#pragma unroll
    for (int o = 16; o > 0; o >>= 1) {
        s += __shfl_xor_sync(0xffffffffu, s, o);
        d += __shfl_xor_sync(0xffffffffu, d, o);
    }
    if (lane == 0) {
        ((float*)&g_T [i])[head] = expf(-s);
        ((float*)&g_A1[i])[head] = expf(s);
        ((float*)&g_Ap[i])[head] = expf(0.2f * s);
        ((float*)&g_E1[i])[head] = expf(d);
        ((float*)&g_Ep[i])[head] = expf(0.2f * d);
    }
}

// ======================= Kernel 2: softmax denominators =======================
// warp-per-row, float4 adj loads, no block barriers. grid NN/8, 256 thr.
__global__ __launch_bounds__(256) void k2_denom(const float* __restrict__ adj) {
    const int wid = threadIdx.x >> 5;
    const int lane = threadIdx.x & 31;
    const int i = blockIdx.x * 8 + wid;
    const float4 T = g_T[i];
    float4 S1 = make_float4(0.f, 0.f, 0.f, 0.f);
    float4 Sp = make_float4(0.f, 0.f, 0.f, 0.f);
    const float4* arow = (const float4*)(adj + (size_t)i * NN);
#pragma unroll 4
    for (int k = 0; k < NN / 128; k++) {       // 32 float4 per lane, independent
        int j4 = k * 32 + lane;
        float4 av = arow[j4];
        int j = j4 * 4;
        float mq[4] = {av.x, av.y, av.z, av.w};
#pragma unroll
        for (int q = 0; q < 4; q++) {
            if (mq[q] > 0.1f) {
                float4 e1 = g_E1[j + q], ep = g_Ep[j + q];
                if (e1.x >= T.x) S1.x += e1.x; else Sp.x += ep.x;
                if (e1.y >= T.y) S1.y += e1.y; else Sp.y += ep.y;
                if (e1.z >= T.z) S1.z += e1.z; else Sp.z += ep.z;
                if (e1.w >= T.w) S1.w += e1.w; else Sp.w += ep.w;
            }
        }
    }
#pragma unroll
    for (int o = 16; o > 0; o >>= 1) {
        S1.x += __shfl_xor_sync(0xffffffffu, S1.x, o);
        S1.y += __shfl_xor_sync(0xffffffffu, S1.y, o);
        S1.z += __shfl_xor_sync(0xffffffffu, S1.z, o);
        S1.w += __shfl_xor_sync(0xffffffffu, S1.w, o);
        Sp.x += __shfl_xor_sync(0xffffffffu, Sp.x, o);
        Sp.y += __shfl_xor_sync(0xffffffffu, Sp.y, o);
        Sp.z += __shfl_xor_sync(0xffffffffu, Sp.z, o);
        Sp.w += __shfl_xor_sync(0xffffffffu, Sp.w, o);
    }
    if (lane == 0) {
        float4 a1 = g_A1[i], ap = g_Ap[i];
        float d0 = a1.x * S1.x + ap.x * Sp.x;
        float d1 = a1.y * S1.y + ap.y * Sp.y;
        float d2 = a1.z * S1.z + ap.z * Sp.z;
        float d3 = a1.w * S1.w + ap.w * Sp.w;
        float i0 = d0 > 0.f ? 1.f / d0 : 0.f;
        float i1 = d1 > 0.f ? 1.f / d1 : 0.f;
        float i2 = d2 > 0.f ? 1.f / d2 : 0.f;
        float i3 = d3 > 0.f ? 1.f / d3 : 0.f;
        g_R1[i] = make_float4(a1.x * i0, a1.y * i1, a1.z * i2, a1.w * i3);
        g_Rp[i] = make_float4(ap.x * i0, ap.y * i1, ap.z * i2, ap.w * i3);
    }
}

// ======================= Kernel 3: tf32 mma.sync split-K, 4x4 warps, double-buffered =======================
// grid (2 n-tiles, 32 i-tiles, 8 splits), 512 thr (16 warps: warp_m=wid&3 m32, warp_n=wid>>2 n32).
// CTA tile 128m x 128n, K-chunk 64, double-buffered sW/sB (one barrier per chunk).
// adj + h for chunk c+1 prefetched to registers during mma of chunk c.
// sW[m][k] stride 68 -> A frag LDS conflict-free; sB[k][n] stride 136 -> B frag conflict-free.
#define KC 64
#define SWA 68
#define SWB 136
#define SA_FL (128 * SWA)                 // 8704 floats per buffer
#define SB_FL (KC * SWB)                  // 8704 floats per buffer
#define K3_SMEM_TOT ((2 * (SA_FL + SB_FL)) * 4 + 3 * 128 * 16)   // 145408 B
__global__ __launch_bounds__(512, 1) void k3_out(const float* __restrict__ adj) {
    extern __shared__ float sm3[];
    float*  sWb = sm3;                               // 2 x [128][68]
    float*  sBb = sm3 + 2 * SA_FL;                   // 2 x [64][136]
    float4* sT  = (float4*)(sm3 + 2 * (SA_FL + SB_FL));
    float4* sR1 = sT + 128;
    float4* sRp = sR1 + 128;

    const int tid = threadIdx.x;
    const int wid = tid >> 5;
    const int lane = tid & 31;
    const int cn0 = blockIdx.x * 128;
    const int row0 = blockIdx.y * 128;
    const int split = blockIdx.z;
    const int jbeg = split * (NN / K3_SPLIT);

    const int warp_m = wid & 3;            // rows warp_m*32 .. +31 (2 m16 frags)
    const int warp_n = wid >> 2;           // cols warp_n*32 .. +31 (4 n8 frags)

    if (tid < 128) {
        sT[tid] = g_T[row0 + tid]; sR1[tid] = g_R1[row0 + tid]; sRp[tid] = g_Rp[row0 + tid];
    }

    // w-phase mapping: thread covers rows mr..mr+3, j-group jg (4 consecutive j)
    const int jg = tid & 15;
    const int mr = (tid >> 4) * 4;
    const float4* adj4 = (const float4*)adj;
    const float4* gh4 = (const float4*)g_h;

    float acc[2][4][4];
#pragma unroll
    for (int mt = 0; mt < 2; mt++)
#pragma unroll
        for (int nf = 0; nf < 4; nf++)
#pragma unroll
            for (int q = 0; q < 4; q++) acc[mt][nf][q] = 0.f;

    // ---- prefetch chunk 0 ----
    float4 aj[4], bj[4];
#pragma unroll
    for (int l = 0; l < 4; l++)
        aj[l] = adj4[(size_t)(row0 + mr + l) * (NN / 4) + (jbeg >> 2) + jg];
#pragma unroll
    for (int l = 0; l < 4; l++) {
        int s = tid + l * 512;
        int k = s >> 5, n4 = s & 31;
        bj[l] = gh4[(size_t)(jbeg + k) * (OUTF / 4) + (cn0 >> 2) + n4];
    }
    __syncthreads();   // sT/sR1/sRp ready

    const int lr = lane >> 2;
    const int lc = lane & 3;

    for (int c = 0; c < 8; c++) {
        const int j0 = jbeg + c * KC;
        float* sW = sWb + (c & 1) * SA_FL;
        float* sB = sBb + (c & 1) * SB_FL;
        const uint32_t* sWu = (const uint32_t*)sW;
        const uint32_t* sBu = (const uint32_t*)sB;

        // ---- store B tile (tf32) ----
#pragma unroll
        for (int l = 0; l < 4; l++) {
            int s = tid + l * 512;
            int k = s >> 5, n4 = s & 31;
            uint32_t* dst = (uint32_t*)&sB[k * SWB + n4 * 4];
            dst[0] = to_tf32_bits(bj[l].x); dst[1] = to_tf32_bits(bj[l].y);
            dst[2] = to_tf32_bits(bj[l].z); dst[3] = to_tf32_bits(bj[l].w);
        }
        // ---- compute + store w tile (tf32) ----
        {
            float4 e1q[4], epq[4];
#pragma unroll
            for (int q = 0; q < 4; q++) {
                e1q[q] = g_E1[j0 + jg * 4 + q];
                epq[q] = g_Ep[j0 + jg * 4 + q];
            }
#pragma unroll
            for (int l = 0; l < 4; l++) {
                int m = mr + l;
                float4 T = sT[m], R1 = sR1[m], Rp = sRp[m];
                float av[4] = {aj[l].x, aj[l].y, aj[l].z, aj[l].w};
                uint32_t wv[4];
#pragma unroll
                for (int q = 0; q < 4; q++) {
                    float w = 0.f;
                    if (av[q] > 0.1f) {
                        float4 e1 = e1q[q], ep = epq[q];
                        float s0 = (e1.x >= T.x) ? R1.x * e1.x : Rp.x * ep.x;
                        float s1 = (e1.y >= T.y) ? R1.y * e1.y : Rp.y * ep.y;
                        float s2 = (e1.z >= T.z) ? R1.z * e1.z : Rp.z * ep.z;
                        float s3 = (e1.w >= T.w) ? R1.w * e1.w : Rp.w * ep.w;
                        w = 0.25f * ((s0 + s1) + (s2 + s3));
                    }
                    wv[q] = to_tf32_bits(w);
                }
                *(uint4*)&sW[m * SWA + jg * 4] = make_uint4(wv[0], wv[1], wv[2], wv[3]);
            }
        }
        __syncthreads();                   // tiles[c&1] ready (only barrier per chunk)

        // ---- prefetch chunk c+1 (overlaps mma below) ----
        if (c < 7) {
            const int jn = j0 + KC;
#pragma unroll
            for (int l = 0; l < 4; l++)
                aj[l] = adj4[(size_t)(row0 + mr + l) * (NN / 4) + (jn >> 2) + jg];
#pragma unroll
            for (int l = 0; l < 4; l++) {
                int s = tid + l * 512;
                int k = s >> 5, n4 = s & 31;
                bj[l] = gh4[(size_t)(jn + k) * (OUTF / 4) + (cn0 >> 2) + n4];
            }
        }

        // ---- mma: 8 k8-steps, 2 m16 x 4 n8 frags per warp ----
#pragma unroll
        for (int ks = 0; ks < 8; ks++) {
            const int k0 = ks * 8;
            uint32_t af[2][4];
#pragma unroll
            for (int mt = 0; mt < 2; mt++) {
                int rm = (warp_m * 32 + mt * 16 + lr) * SWA + k0 + lc;
                af[mt][0] = sWu[rm];
                af[mt][1] = sWu[rm + 8 * SWA];
                af[mt][2] = sWu[rm + 4];
                af[mt][3] = sWu[rm + 8 * SWA + 4];
            }
#pragma unroll
            for (int nf = 0; nf < 4; nf++) {
                int nb = (k0 + lc) * SWB + warp_n * 32 + nf * 8 + lr;
                uint32_t b0 = sBu[nb];
                uint32_t b1 = sBu[nb + 4 * SWB];
                mma_tf32(acc[0][nf], af[0][0], af[0][1], af[0][2], af[0][3], b0, b1);
                mma_tf32(acc[1][nf], af[1][0], af[1][1], af[1][2], af[1][3], b0, b1);
            }
        }
    }
    // ---- epilogue: fragment-mapped stores to split partials ----
    float* pbase = g_part + (size_t)split * NN * OUTF;
#pragma unroll
    for (int mt = 0; mt < 2; mt++) {
        int r0g = row0 + warp_m * 32 + mt * 16 + lr;
#pragma unroll
        for (int nf = 0; nf < 4; nf++) {
            int col = cn0 + warp_n * 32 + nf * 8 + 2 * lc;
            *(float2*)&pbase[(size_t)r0g * OUTF + col] =
                make_float2(acc[mt][nf][0], acc[mt][nf][1]);
            *(float2*)&pbase[(size_t)(r0g + 8) * OUTF + col] =
                make_float2(acc[mt][nf][2], acc[mt][nf][3]);
        }
    }
}

// ======================= Kernel 4: reduce splits + bias =======================
__global__ __launch_bounds__(256) void k4_reduce(const float* __restrict__ bias,
                                                 float* __restrict__ out) {
    int idx = blockIdx.x * 256 + threadIdx.x;
    int col4 = idx & (OUTF / 4 - 1);
    float4 s = ((const float4*)bias)[col4];
    const float4* p = (const float4*)g_part;
#pragma unroll
    for (int k = 0; k < K3_SPLIT; k++) {
        float4 v = p[(size_t)k * (NN * OUTF / 4) + idx];
        s.x += v.x; s.y += v.y; s.z += v.z; s.w += v.w;
    }
    ((float4*)out)[idx] = s;
}

// ======================= launch =======================
extern "C" void kernel_launch(void* const* d_in, const int* in_sizes, int n_in,
                              void* d_out, int out_size) {
    const float* features = (const float*)d_in[0];
    const float* adj      = (const float*)d_in[1];
    const float* W        = (const float*)d_in[2];
    const float* a        = (const float*)d_in[3];
    const float* bias     = (const float*)d_in[4];
    float* out = (float*)d_out;

    cudaFuncSetAttribute(k3_out, cudaFuncAttributeMaxDynamicSharedMemorySize, K3_SMEM_TOT);

    k1_gemm<<<dim3(OUTF / 64, NN / 64), 128>>>(features, W);
    k1b_stats<<<NN, 128>>>(a);
    k2_denom<<<NN / 8, 256>>>(adj);
    k3_out<<<dim3(2, NN / 128, K3_SPLIT), 512, K3_SMEM_TOT>>>(adj);
    k4_reduce<<<NN * OUTF / 4 / 256, 256>>>(bias, out);
}